// round 1
// baseline (speedup 1.0000x reference)
#include <cuda_runtime.h>
#include <math.h>
#include <stdint.h>

#define BB 8
#define NN 8192
#define SS 2048
#define NSAMP 32
#define NSAMPLES (BB*SS*NSAMP)   /* 524288 */
#define NGROUPS (BB*SS)          /* 16384  */
#define R2 0.04f
#define BNEPS 1e-5f

// ---------------- device scratch (static: no allocations allowed) ----------------
__device__ float g_feat[(size_t)NSAMPLES*8];     // [sample][8] (6 used, padded)
__device__ float g_x2[(size_t)NSAMPLES*64];      // layer-2 pre-BN activations
__device__ float g_gmax[(size_t)NGROUPS*128];    // per-(b,s) max of x3 over neighbors
__device__ float g_gmin[(size_t)NGROUPS*128];
__device__ float g_fsum[6];
__device__ float g_fmom[21];
__device__ float g_x2sum[64], g_x2sq[64];
__device__ float g_x3sum[128], g_x3sq[128];
__device__ float g_W1s[64*6], g_b1s[64];         // BN1 folded into W1
__device__ float g_sc2[64], g_sh2[64];
__device__ float g_sc3[128], g_sh3[128];

// ---------------- K0: zero accumulators (graph-replay safe) ----------------
__global__ void k_zero() {
    int t = threadIdx.x;
    if (t < 6)  g_fsum[t] = 0.f;
    if (t < 21) g_fmom[t] = 0.f;
    if (t < 64) { g_x2sum[t] = 0.f; g_x2sq[t] = 0.f; }
    if (t < 128){ g_x3sum[t] = 0.f; g_x3sq[t] = 0.f; }
}

// ---------------- K1: ball query + feat + feat moments + out1 ----------------
// grid (S/32, B), 256 threads. xyz[b] staged in SMEM (96KB). 1 warp = 4 queries.
__global__ __launch_bounds__(256) void k_ball(const float* __restrict__ xyz,
                                              const float* __restrict__ points,
                                              const int*   __restrict__ fps,
                                              float* __restrict__ out1) {
    extern __shared__ float sm[];
    float* sx = sm;
    float* sy = sm + NN;
    float* sz = sm + 2*NN;
    int*   fnd = (int*)(sm + 3*NN);   // [8 warps][32]

    int b = blockIdx.y;
    int qbase = blockIdx.x * 32;
    int tid = threadIdx.x;

    for (int i = tid; i < NN; i += 256) {
        sx[i] = xyz[(b*3+0)*NN + i];
        sy[i] = xyz[(b*3+1)*NN + i];
        sz[i] = xyz[(b*3+2)*NN + i];
    }
    __syncthreads();

    int w = tid >> 5, lane = tid & 31;
    int* f = fnd + w*32;
    unsigned lmask = (1u << lane) - 1u;

    float s1[6], s2[21];
    #pragma unroll
    for (int i = 0; i < 6; i++)  s1[i] = 0.f;
    #pragma unroll
    for (int i = 0; i < 21; i++) s2[i] = 0.f;

    for (int qi = 0; qi < 4; qi++) {
        int s = qbase + w*4 + qi;
        int cidx = fps[b*SS + s];
        float cx = sx[cidx], cy = sy[cidx], cz = sz[cidx];
        if (lane == 0) {
            out1[(b*3+0)*SS + s] = cx;
            out1[(b*3+1)*SS + s] = cy;
            out1[(b*3+2)*SS + s] = cz;
        }
        int cnt = 0;
        for (int chunk = 0; chunk < NN/32; chunk++) {
            int j = chunk*32 + lane;
            // match reference rounding: no fma contraction in the distance
            float dx = __fsub_rn(sx[j], cx);
            float dy = __fsub_rn(sy[j], cy);
            float dz = __fsub_rn(sz[j], cz);
            float d2 = __fadd_rn(__fadd_rn(__fmul_rn(dx,dx), __fmul_rn(dy,dy)),
                                 __fmul_rn(dz,dz));
            bool hit = (d2 <= R2);
            unsigned mask = __ballot_sync(0xffffffffu, hit);
            if (hit) {
                int pos = cnt + __popc(mask & lmask);
                if (pos < 32) f[pos] = j;
            }
            cnt += __popc(mask);
            if (cnt >= 32) break;        // uniform across warp
        }
        __syncwarp();
        int j = (lane < cnt) ? f[lane] : f[0];   // pad with first hit (self always hits)
        __syncwarp();

        float fx = sx[j]-cx, fy = sy[j]-cy, fz = sz[j]-cz;
        float p0 = points[(b*3+0)*NN + j];
        float p1 = points[(b*3+1)*NN + j];
        float p2 = points[(b*3+2)*NN + j];

        size_t base = ((size_t)(b*SS + s)*NSAMP + lane) * 8;
        *(float4*)(g_feat + base)     = make_float4(fx, fy, fz, p0);
        *(float4*)(g_feat + base + 4) = make_float4(p1, p2, 0.f, 0.f);

        float fv[6] = {fx, fy, fz, p0, p1, p2};
        int k = 0;
        #pragma unroll
        for (int c = 0; c < 6; c++) {
            s1[c] += fv[c];
            #pragma unroll
            for (int c2 = 0; c2 <= c; c2++) s2[k++] += fv[c]*fv[c2];
        }
    }

    // block-reduce 27 moment partials -> global atomics
    __shared__ float red[27];
    if (tid < 27) red[tid] = 0.f;
    __syncthreads();
    #pragma unroll
    for (int i = 0; i < 6; i++) {
        float v = s1[i];
        for (int off = 16; off; off >>= 1) v += __shfl_down_sync(0xffffffffu, v, off);
        if (lane == 0) atomicAdd(&red[i], v);
    }
    #pragma unroll
    for (int i = 0; i < 21; i++) {
        float v = s2[i];
        for (int off = 16; off; off >>= 1) v += __shfl_down_sync(0xffffffffu, v, off);
        if (lane == 0) atomicAdd(&red[6+i], v);
    }
    __syncthreads();
    if (tid < 6)                 atomicAdd(&g_fsum[tid], red[tid]);
    else if (tid < 27)           atomicAdd(&g_fmom[tid-6], red[tid]);
}

// ---------------- K2: BN1 params from feat moments, folded into W1 ----------------
__global__ void k_bn1(const float* __restrict__ W1, const float* __restrict__ g1,
                      const float* __restrict__ b1) {
    __shared__ float mu[6], C[6][6];
    int o = threadIdx.x;  // 64
    if (o == 0) {
        const float inv = 1.0f / (float)NSAMPLES;
        for (int c = 0; c < 6; c++) mu[c] = g_fsum[c]*inv;
        int k = 0;
        for (int c = 0; c < 6; c++)
            for (int c2 = 0; c2 <= c; c2++) {
                float v = g_fmom[k++]*inv; C[c][c2] = v; C[c2][c] = v;
            }
    }
    __syncthreads();
    float w[6];
    #pragma unroll
    for (int c = 0; c < 6; c++) w[c] = W1[o*6+c];
    float mean = 0.f;
    #pragma unroll
    for (int c = 0; c < 6; c++) mean += w[c]*mu[c];
    float e2 = 0.f;
    #pragma unroll
    for (int c = 0; c < 6; c++) {
        float t = 0.f;
        #pragma unroll
        for (int c2 = 0; c2 < 6; c2++) t += C[c][c2]*w[c2];
        e2 += w[c]*t;
    }
    float var = fmaxf(e2 - mean*mean, 0.f);
    float sc = g1[o]*rsqrtf(var + BNEPS);
    #pragma unroll
    for (int c = 0; c < 6; c++) g_W1s[o*6+c] = w[c]*sc;
    g_b1s[o] = b1[o] - mean*sc;
}

// ---------------- K3: feat -> h1 -> x2 (+stats, store x2) ----------------
// grid 4096, 256 threads, tile = 128 samples.
__global__ __launch_bounds__(256) void k_l1l2(const float* __restrict__ W2) {
    extern __shared__ float sm[];
    float* sW1  = sm;                 // 384
    float* sB1  = sm + 384;           // 64
    float* sWt  = sm + 448;           // 64*68 = 4352  (Wt[k][o], padded)
    float* sH   = sm + 448 + 4352;    // 64*132 = 8448 (h1[k][s], padded)
    float* csum = sm + 448 + 4352 + 8448;  // 64
    float* csq  = csum + 64;               // 64

    int t = threadIdx.x;
    for (int i = t; i < 384; i += 256) sW1[i] = g_W1s[i];
    if (t < 64) { sB1[t] = g_b1s[t]; csum[t] = 0.f; csq[t] = 0.f; }
    for (int i = t; i < 4096; i += 256) { int o = i >> 6, k = i & 63; sWt[k*68 + o] = W2[i]; }
    __syncthreads();

    size_t s0 = (size_t)blockIdx.x * 128;

    // step A: h1 tile (transposed [k][s])
    {
        int s = t & 127, kb = t >> 7;
        const float* fp = g_feat + (s0 + s)*8;
        float4 f0 = *(const float4*)fp;
        float4 f1 = *(const float4*)(fp + 4);
        float f[6] = {f0.x, f0.y, f0.z, f0.w, f1.x, f1.y};
        #pragma unroll 8
        for (int kk = 0; kk < 32; kk++) {
            int k = kb*32 + kk;
            float acc = sB1[k];
            #pragma unroll
            for (int c = 0; c < 6; c++) acc += f[c]*sW1[k*6+c];
            sH[k*132 + s] = fmaxf(acc, 0.f);
        }
    }
    __syncthreads();

    // step B: x2 = h1 @ W2^T, 4 channels x 8 samples per thread
    int to = t & 15, ts = t >> 4;
    float acc[4][8];
    #pragma unroll
    for (int i = 0; i < 4; i++)
        #pragma unroll
        for (int j = 0; j < 8; j++) acc[i][j] = 0.f;

    #pragma unroll 4
    for (int k = 0; k < 64; k++) {
        float4 h0 = *(float4*)&sH[k*132 + ts*8];
        float4 h1 = *(float4*)&sH[k*132 + ts*8 + 4];
        float4 wv = *(float4*)&sWt[k*68 + to*4];
        float hv[8] = {h0.x,h0.y,h0.z,h0.w,h1.x,h1.y,h1.z,h1.w};
        float wa[4] = {wv.x,wv.y,wv.z,wv.w};
        #pragma unroll
        for (int i = 0; i < 4; i++)
            #pragma unroll
            for (int j = 0; j < 8; j++) acc[i][j] += wa[i]*hv[j];
    }

    #pragma unroll
    for (int i = 0; i < 4; i++) {
        float ps = 0.f, pq = 0.f;
        #pragma unroll
        for (int j = 0; j < 8; j++) { float x = acc[i][j]; ps += x; pq += x*x; }
        atomicAdd(&csum[to*4+i], ps);
        atomicAdd(&csq[to*4+i], pq);
    }
    #pragma unroll
    for (int j = 0; j < 8; j++) {
        size_t sg = s0 + ts*8 + j;
        *(float4*)(g_x2 + sg*64 + to*4) = make_float4(acc[0][j], acc[1][j], acc[2][j], acc[3][j]);
    }
    __syncthreads();
    if (t < 64) { atomicAdd(&g_x2sum[t], csum[t]); atomicAdd(&g_x2sq[t], csq[t]); }
}

// ---------------- K4: BN2 params ----------------
__global__ void k_bn2(const float* __restrict__ g2, const float* __restrict__ b2) {
    int o = threadIdx.x;  // 64
    const float inv = 1.0f / (float)NSAMPLES;
    float m = g_x2sum[o]*inv;
    float v = fmaxf(g_x2sq[o]*inv - m*m, 0.f);
    float sc = g2[o]*rsqrtf(v + BNEPS);
    g_sc2[o] = sc; g_sh2[o] = b2[o] - m*sc;
}

// ---------------- K5: x2 -> h2 -> x3 (+stats, per-group max/min) ----------------
// grid 4096, 256 threads, tile = 128 samples = 4 neighbor-groups.
__global__ __launch_bounds__(256) void k_l3(const float* __restrict__ W3) {
    extern __shared__ float sm[];
    float* sWt3 = sm;              // 64*132 = 8448 (Wt3[k][o], o<128)
    float* sH2  = sm + 8448;       // 64*132 = 8448
    float* ssc2 = sm + 16896;      // 64
    float* ssh2 = ssc2 + 64;       // 64
    float* csum = ssh2 + 64;       // 128
    float* csq  = csum + 128;      // 128

    int t = threadIdx.x;
    if (t < 64)  { ssc2[t] = g_sc2[t]; ssh2[t] = g_sh2[t]; }
    if (t < 128) { csum[t] = 0.f; csq[t] = 0.f; }
    for (int i = t; i < 8192; i += 256) { int o = i >> 6, k = i & 63; sWt3[k*132 + o] = W3[i]; }
    __syncthreads();

    size_t s0 = (size_t)blockIdx.x * 128;

    // step A: load x2, apply bn2+relu, store transposed [k][s]
    for (int i = t; i < 2048; i += 256) {
        int s = i >> 4, kq = i & 15;
        float4 v = *(const float4*)(g_x2 + (s0 + s)*64 + kq*4);
        int k = kq*4;
        sH2[(k+0)*132 + s] = fmaxf(v.x*ssc2[k+0] + ssh2[k+0], 0.f);
        sH2[(k+1)*132 + s] = fmaxf(v.y*ssc2[k+1] + ssh2[k+1], 0.f);
        sH2[(k+2)*132 + s] = fmaxf(v.z*ssc2[k+2] + ssh2[k+2], 0.f);
        sH2[(k+3)*132 + s] = fmaxf(v.w*ssc2[k+3] + ssh2[k+3], 0.f);
    }
    __syncthreads();

    // step B: x3 = h2 @ W3^T, 8 channels x 8 samples per thread
    int to = t & 15, ts = t >> 4;
    float acc[8][8];
    #pragma unroll
    for (int i = 0; i < 8; i++)
        #pragma unroll
        for (int j = 0; j < 8; j++) acc[i][j] = 0.f;

    #pragma unroll 2
    for (int k = 0; k < 64; k++) {
        float4 h0 = *(float4*)&sH2[k*132 + ts*8];
        float4 h1 = *(float4*)&sH2[k*132 + ts*8 + 4];
        float4 w0 = *(float4*)&sWt3[k*132 + to*8];
        float4 w1 = *(float4*)&sWt3[k*132 + to*8 + 4];
        float hv[8] = {h0.x,h0.y,h0.z,h0.w,h1.x,h1.y,h1.z,h1.w};
        float wv[8] = {w0.x,w0.y,w0.z,w0.w,w1.x,w1.y,w1.z,w1.w};
        #pragma unroll
        for (int i = 0; i < 8; i++)
            #pragma unroll
            for (int j = 0; j < 8; j++) acc[i][j] += wv[i]*hv[j];
    }

    // stats + per-thread max/min over this thread's 8 samples (all in one group)
    float pmax[8], pmin[8];
    #pragma unroll
    for (int i = 0; i < 8; i++) {
        float ps = 0.f, pq = 0.f, mx = -INFINITY, mn = INFINITY;
        #pragma unroll
        for (int j = 0; j < 8; j++) {
            float x = acc[i][j];
            ps += x; pq += x*x; mx = fmaxf(mx, x); mn = fminf(mn, x);
        }
        atomicAdd(&csum[to*8+i], ps);
        atomicAdd(&csq[to*8+i], pq);
        pmax[i] = mx; pmin[i] = mn;
    }
    __syncthreads();                 // done with sWt3 -> reuse for reductions
    float* rmax = sWt3;              // [16][128]
    float* rmin = sWt3 + 2048;       // [16][128]
    #pragma unroll
    for (int i = 0; i < 8; i++) {
        rmax[ts*128 + to*8 + i] = pmax[i];
        rmin[ts*128 + to*8 + i] = pmin[i];
    }
    __syncthreads();
    for (int v = t; v < 512; v += 256) {
        int gq = v >> 7, o = v & 127;
        float mx = rmax[(gq*4+0)*128 + o];
        mx = fmaxf(mx, rmax[(gq*4+1)*128 + o]);
        mx = fmaxf(mx, rmax[(gq*4+2)*128 + o]);
        mx = fmaxf(mx, rmax[(gq*4+3)*128 + o]);
        float mn = rmin[(gq*4+0)*128 + o];
        mn = fminf(mn, rmin[(gq*4+1)*128 + o]);
        mn = fminf(mn, rmin[(gq*4+2)*128 + o]);
        mn = fminf(mn, rmin[(gq*4+3)*128 + o]);
        size_t g = s0/32 + gq;
        g_gmax[g*128 + o] = mx;
        g_gmin[g*128 + o] = mn;
    }
    __syncthreads();
    if (t < 128) { atomicAdd(&g_x3sum[t], csum[t]); atomicAdd(&g_x3sq[t], csq[t]); }
}

// ---------------- K6: BN3 params ----------------
__global__ void k_bn3(const float* __restrict__ g3, const float* __restrict__ b3) {
    int o = threadIdx.x;  // 128
    const float inv = 1.0f / (float)NSAMPLES;
    float m = g_x3sum[o]*inv;
    float v = fmaxf(g_x3sq[o]*inv - m*m, 0.f);
    float sc = g3[o]*rsqrtf(v + BNEPS);
    g_sc3[o] = sc; g_sh3[o] = b3[o] - m*sc;
}

// ---------------- K7: final bn3+relu on group max/min, transposed output ----------------
// grid (S/32, B), 256 threads. max(relu(bn(x))) = relu(sc>=0 ? sc*max+sh : sc*min+sh).
__global__ void k_out2(float* __restrict__ out2) {
    __shared__ float tr[32*129];
    int b = blockIdx.y;
    int s0 = blockIdx.x * 32;
    for (int i = threadIdx.x; i < 32*128; i += 256) {
        int gi = i >> 7, o = i & 127;
        float sc = g_sc3[o], sh = g_sh3[o];
        size_t g = (size_t)(b*SS + s0 + gi);
        float v = (sc >= 0.f) ? g_gmax[g*128 + o] : g_gmin[g*128 + o];
        tr[gi*129 + o] = fmaxf(sc*v + sh, 0.f);
    }
    __syncthreads();
    for (int i = threadIdx.x; i < 32*128; i += 256) {
        int o = i >> 5, si = i & 31;
        out2[((size_t)(b*128 + o))*SS + s0 + si] = tr[si*129 + o];
    }
}

// ---------------- launch ----------------
extern "C" void kernel_launch(void* const* d_in, const int* in_sizes, int n_in,
                              void* d_out, int out_size) {
    const float* xyz    = (const float*)d_in[0];
    const float* points = (const float*)d_in[1];
    const int*   fps    = (const int*)  d_in[2];
    const float* W1 = (const float*)d_in[3];
    const float* g1 = (const float*)d_in[4];
    const float* b1 = (const float*)d_in[5];
    const float* W2 = (const float*)d_in[6];
    const float* g2 = (const float*)d_in[7];
    const float* b2 = (const float*)d_in[8];
    const float* W3 = (const float*)d_in[9];
    const float* g3 = (const float*)d_in[10];
    const float* b3 = (const float*)d_in[11];

    float* out1 = (float*)d_out;                       // [B,3,S]
    float* out2 = (float*)d_out + (size_t)BB*3*SS;     // [B,128,S]

    const int SMEM1 = (3*NN)*4 + 8*32*4;               // 99328
    const int SMEM3 = (448 + 4352 + 8448 + 128)*4;     // 53504
    const int SMEM5 = (8448 + 8448 + 64 + 64 + 128 + 128)*4;  // 69120

    cudaFuncSetAttribute(k_ball,  cudaFuncAttributeMaxDynamicSharedMemorySize, SMEM1);
    cudaFuncSetAttribute(k_l1l2,  cudaFuncAttributeMaxDynamicSharedMemorySize, SMEM3);
    cudaFuncSetAttribute(k_l3,    cudaFuncAttributeMaxDynamicSharedMemorySize, SMEM5);

    k_zero<<<1, 128>>>();
    k_ball<<<dim3(SS/32, BB), 256, SMEM1>>>(xyz, points, fps, out1);
    k_bn1<<<1, 64>>>(W1, g1, b1);
    k_l1l2<<<NSAMPLES/128, 256, SMEM3>>>(W2);
    k_bn2<<<1, 64>>>(g2, b2);
    k_l3<<<NSAMPLES/128, 256, SMEM5>>>(W3);
    k_bn3<<<1, 128>>>(g3, b3);
    k_out2<<<dim3(SS/32, BB), 256>>>(out2);
}

// round 2
// speedup vs baseline: 1.2338x; 1.2338x over previous
#include <cuda_runtime.h>
#include <math.h>
#include <stdint.h>

#define BB 8
#define NN 8192
#define SS 2048
#define NSAMP 32
#define NSAMPLES (BB*SS*NSAMP)   /* 524288 */
#define NGROUPS (BB*SS)          /* 16384  */
#define NTILES (NSAMPLES/128)    /* 4096   */
#define R2 0.04f
#define BNEPS 1e-5f

typedef unsigned long long ull;

// ---------------- device scratch ----------------
__device__ float g_feat[(size_t)NSAMPLES*8];     // [sample][8] (6 used)
__device__ float g_gmax[(size_t)NGROUPS*128];
__device__ float g_gmin[(size_t)NGROUPS*128];
__device__ float g_fsum[6];
__device__ float g_fmom[21];
__device__ float g_M[64*64];                     // sum over samples of h1 h1^T
__device__ float g_h1sum[64];
__device__ float g_x3sum[128], g_x3sq[128];
__device__ float g_W1s[64*6], g_b1s[64];         // BN1 folded into W1
__device__ float g_sc2[64], g_sh2[64];
__device__ float g_sc3[128], g_sh3[128];

// ---------------- f32x2 helpers ----------------
static __device__ __forceinline__ void fma2(ull& d, ull a, ull b) {
    asm("fma.rn.f32x2 %0, %1, %2, %0;" : "+l"(d) : "l"(a), "l"(b));
}
static __device__ __forceinline__ float hadd2(ull v) {
    float lo, hi;
    asm("mov.b64 {%0,%1}, %2;" : "=f"(lo), "=f"(hi) : "l"(v));
    return lo + hi;
}

// ---------------- K0: zero accumulators ----------------
__global__ void k_zero() {
    int t = threadIdx.x;
    for (int i = t; i < 4096; i += 256) g_M[i] = 0.f;
    if (t < 6)  g_fsum[t] = 0.f;
    if (t < 21) g_fmom[t] = 0.f;
    if (t < 64) g_h1sum[t] = 0.f;
    if (t < 128){ g_x3sum[t] = 0.f; g_x3sq[t] = 0.f; }
}

// ---------------- K1: ball query + feat + feat moments + out1 ----------------
__global__ __launch_bounds__(256) void k_ball(const float* __restrict__ xyz,
                                              const float* __restrict__ points,
                                              const int*   __restrict__ fps,
                                              float* __restrict__ out1) {
    extern __shared__ float sm[];
    float* sx = sm;
    float* sy = sm + NN;
    float* sz = sm + 2*NN;
    int*   fnd = (int*)(sm + 3*NN);   // [8 warps][32]

    int b = blockIdx.y;
    int qbase = blockIdx.x * 32;
    int tid = threadIdx.x;

    for (int i = tid; i < NN; i += 256) {
        sx[i] = xyz[(b*3+0)*NN + i];
        sy[i] = xyz[(b*3+1)*NN + i];
        sz[i] = xyz[(b*3+2)*NN + i];
    }
    __syncthreads();

    int w = tid >> 5, lane = tid & 31;
    int* f = fnd + w*32;
    unsigned lmask = (1u << lane) - 1u;

    float s1[6], s2[21];
    #pragma unroll
    for (int i = 0; i < 6; i++)  s1[i] = 0.f;
    #pragma unroll
    for (int i = 0; i < 21; i++) s2[i] = 0.f;

    for (int qi = 0; qi < 4; qi++) {
        int s = qbase + w*4 + qi;
        int cidx = fps[b*SS + s];
        float cx = sx[cidx], cy = sy[cidx], cz = sz[cidx];
        if (lane == 0) {
            out1[(b*3+0)*SS + s] = cx;
            out1[(b*3+1)*SS + s] = cy;
            out1[(b*3+2)*SS + s] = cz;
        }
        int cnt = 0;
        for (int chunk = 0; chunk < NN/32; chunk++) {
            int j = chunk*32 + lane;
            float dx = __fsub_rn(sx[j], cx);
            float dy = __fsub_rn(sy[j], cy);
            float dz = __fsub_rn(sz[j], cz);
            float d2 = __fadd_rn(__fadd_rn(__fmul_rn(dx,dx), __fmul_rn(dy,dy)),
                                 __fmul_rn(dz,dz));
            bool hit = (d2 <= R2);
            unsigned mask = __ballot_sync(0xffffffffu, hit);
            if (hit) {
                int pos = cnt + __popc(mask & lmask);
                if (pos < 32) f[pos] = j;
            }
            cnt += __popc(mask);
            if (cnt >= 32) break;
        }
        __syncwarp();
        int j = (lane < cnt) ? f[lane] : f[0];
        __syncwarp();

        float fx = sx[j]-cx, fy = sy[j]-cy, fz = sz[j]-cz;
        float p0 = points[(b*3+0)*NN + j];
        float p1 = points[(b*3+1)*NN + j];
        float p2 = points[(b*3+2)*NN + j];

        size_t base = ((size_t)(b*SS + s)*NSAMP + lane) * 8;
        *(float4*)(g_feat + base)     = make_float4(fx, fy, fz, p0);
        *(float4*)(g_feat + base + 4) = make_float4(p1, p2, 0.f, 0.f);

        float fv[6] = {fx, fy, fz, p0, p1, p2};
        int k = 0;
        #pragma unroll
        for (int c = 0; c < 6; c++) {
            s1[c] += fv[c];
            #pragma unroll
            for (int c2 = 0; c2 <= c; c2++) s2[k++] += fv[c]*fv[c2];
        }
    }

    __shared__ float red[27];
    if (tid < 27) red[tid] = 0.f;
    __syncthreads();
    #pragma unroll
    for (int i = 0; i < 6; i++) {
        float v = s1[i];
        for (int off = 16; off; off >>= 1) v += __shfl_down_sync(0xffffffffu, v, off);
        if (lane == 0) atomicAdd(&red[i], v);
    }
    #pragma unroll
    for (int i = 0; i < 21; i++) {
        float v = s2[i];
        for (int off = 16; off; off >>= 1) v += __shfl_down_sync(0xffffffffu, v, off);
        if (lane == 0) atomicAdd(&red[6+i], v);
    }
    __syncthreads();
    if (tid < 6)       atomicAdd(&g_fsum[tid], red[tid]);
    else if (tid < 27) atomicAdd(&g_fmom[tid-6], red[tid]);
}

// ---------------- K2: BN1 fold ----------------
__global__ void k_bn1(const float* __restrict__ W1, const float* __restrict__ g1,
                      const float* __restrict__ b1) {
    __shared__ float mu[6], C[6][6];
    int o = threadIdx.x;  // 64
    if (o == 0) {
        const float inv = 1.0f / (float)NSAMPLES;
        for (int c = 0; c < 6; c++) mu[c] = g_fsum[c]*inv;
        int k = 0;
        for (int c = 0; c < 6; c++)
            for (int c2 = 0; c2 <= c; c2++) {
                float v = g_fmom[k++]*inv; C[c][c2] = v; C[c2][c] = v;
            }
    }
    __syncthreads();
    float w[6];
    #pragma unroll
    for (int c = 0; c < 6; c++) w[c] = W1[o*6+c];
    float mean = 0.f;
    #pragma unroll
    for (int c = 0; c < 6; c++) mean += w[c]*mu[c];
    float e2 = 0.f;
    #pragma unroll
    for (int c = 0; c < 6; c++) {
        float t = 0.f;
        #pragma unroll
        for (int c2 = 0; c2 < 6; c2++) t += C[c][c2]*w[c2];
        e2 += w[c]*t;
    }
    float var = fmaxf(e2 - mean*mean, 0.f);
    float sc = g1[o]*rsqrtf(var + BNEPS);
    #pragma unroll
    for (int c = 0; c < 6; c++) g_W1s[o*6+c] = w[c]*sc;
    g_b1s[o] = b1[o] - mean*sc;
}

// ---------------- K3: stats pass — h1 mean + SYRK M = sum h1 h1^T ----------------
// grid 592 blocks x 256 thr; each block loops over tiles (128 samples each).
// smem h1 layout [k][s] (row pad 134) so s-pairs are contiguous for f32x2.
#define P1PAD 134
__global__ __launch_bounds__(256) void k_stats() {
    extern __shared__ float sm[];
    float* sW1  = sm;              // 384
    float* sB1  = sm + 384;        // 64
    float* ssum = sm + 448;        // 64
    float* sH   = sm + 512;        // 64*134

    int t = threadIdx.x;
    for (int i = t; i < 384; i += 256) sW1[i] = g_W1s[i];
    if (t < 64) { sB1[t] = g_b1s[t]; ssum[t] = 0.f; }
    __syncthreads();

    int to = t & 15, ts = t >> 4;
    ull accM[16];
    #pragma unroll
    for (int i = 0; i < 16; i++) accM[i] = 0ull;

    for (int tile = blockIdx.x; tile < NTILES; tile += gridDim.x) {
        size_t s0 = (size_t)tile * 128;
        // h1 tile: thread handles sample s, 32 k's
        {
            int s = t & 127, kb = t >> 7;
            const float* fp = g_feat + (s0 + s)*8;
            float4 f0 = *(const float4*)fp;
            float4 f1 = *(const float4*)(fp + 4);
            float f[6] = {f0.x, f0.y, f0.z, f0.w, f1.x, f1.y};
            #pragma unroll 8
            for (int kk = 0; kk < 32; kk++) {
                int k = kb*32 + kk;
                float acc = sB1[k];
                #pragma unroll
                for (int c = 0; c < 6; c++) acc += f[c]*sW1[k*6+c];
                sH[k*P1PAD + s] = fmaxf(acc, 0.f);
            }
        }
        __syncthreads();
        // per-channel sums
        {
            int k = t & 63, q = t >> 6;
            float local = 0.f;
            #pragma unroll 8
            for (int m = 0; m < 32; m++) local += sH[k*P1PAD + q*32 + m];
            atomicAdd(&ssum[k], local);
        }
        // SYRK: M[a][b] += sum_s h[a][s]*h[b][s], a = ts+16i, b = to+16j
        {
            const ull* ra[4]; const ull* rb[4];
            #pragma unroll
            for (int i = 0; i < 4; i++) ra[i] = (const ull*)&sH[(ts + 16*i)*P1PAD];
            #pragma unroll
            for (int j = 0; j < 4; j++) rb[j] = (const ull*)&sH[(to + 16*j)*P1PAD];
            #pragma unroll 2
            for (int s2 = 0; s2 < 64; s2++) {
                ull ha[4], hb[4];
                #pragma unroll
                for (int i = 0; i < 4; i++) ha[i] = ra[i][s2];
                #pragma unroll
                for (int j = 0; j < 4; j++) hb[j] = rb[j][s2];
                #pragma unroll
                for (int i = 0; i < 4; i++)
                    #pragma unroll
                    for (int j = 0; j < 4; j++) fma2(accM[i*4+j], ha[i], hb[j]);
            }
        }
        __syncthreads();
    }

    #pragma unroll
    for (int i = 0; i < 4; i++)
        #pragma unroll
        for (int j = 0; j < 4; j++)
            atomicAdd(&g_M[(ts + 16*i)*64 + (to + 16*j)], hadd2(accM[i*4+j]));
    __syncthreads();
    if (t < 64) atomicAdd(&g_h1sum[t], ssum[t]);
}

// ---------------- K4: BN2 params from M / h1sum ----------------
__global__ void k_bn2(const float* __restrict__ W2, const float* __restrict__ g2,
                      const float* __restrict__ b2) {
    __shared__ float hm[64], mb[128], qb[128];
    int t = threadIdx.x;  // 128
    if (t < 64) hm[t] = g_h1sum[t] * (1.0f/(float)NSAMPLES);
    __syncthreads();
    int o = t & 63, half = t >> 6;
    float lm = 0.f, lq = 0.f;
    for (int k = half*32; k < half*32 + 32; k++) {
        float w = W2[o*64 + k];
        lm += w*hm[k];
        float s = 0.f;
        #pragma unroll 4
        for (int k2 = 0; k2 < 64; k2++) s += g_M[k*64 + k2]*W2[o*64 + k2];
        lq += w*s;
    }
    mb[t] = lm; qb[t] = lq;
    __syncthreads();
    if (t < 64) {
        float m = mb[t] + mb[t+64];
        float q = (qb[t] + qb[t+64]) * (1.0f/(float)NSAMPLES);
        float var = fmaxf(q - m*m, 0.f);
        float sc = g2[t]*rsqrtf(var + BNEPS);
        g_sc2[t] = sc; g_sh2[t] = b2[t] - m*sc;
    }
}

// ---------------- K5: fused feat->h1->x2->bn2/relu->x3 (+stats, group max/min) ----
// grid 4096, 256 thr, tile = 128 samples = 4 neighbor-groups.
// sW2/sW3 layout [o][k] pad 66; sH layout [s][k] pad 68 (k-pairs contiguous).
#define WPAD 66
#define HPAD 68
__global__ __launch_bounds__(256, 2) void k_fused(const float* __restrict__ W2,
                                                  const float* __restrict__ W3) {
    extern __shared__ float sm[];
    float* sW1  = sm;                  // 384
    float* sB1  = sm + 384;            // 64
    float* sc2s = sm + 448;            // 64
    float* sh2s = sm + 512;            // 64
    float* csum = sm + 576;            // 128
    float* csq  = sm + 704;            // 128
    float* sW2  = sm + 832;            // 64*66  = 4224
    float* sW3  = sm + 5056;           // 128*66 = 8448
    float* sH   = sm + 13504;          // 128*68 = 8704
    float* rmax = sm + 832;            // reuse sW2 after GEMM1: [16][128]
    float* rmin = sm + 832 + 2048;

    int t = threadIdx.x;
    for (int i = t; i < 384; i += 256) sW1[i] = g_W1s[i];
    if (t < 64) { sB1[t] = g_b1s[t]; sc2s[t] = g_sc2[t]; sh2s[t] = g_sh2[t]; }
    if (t < 128){ csum[t] = 0.f; csq[t] = 0.f; }
    for (int i = t; i < 4096; i += 256) { int o = i >> 6, k = i & 63; sW2[o*WPAD + k] = W2[i]; }
    for (int i = t; i < 8192; i += 256) { int o = i >> 6, k = i & 63; sW3[o*WPAD + k] = W3[i]; }
    __syncthreads();

    size_t s0 = (size_t)blockIdx.x * 128;

    // step A: h1 into sH[s][k]
    {
        int s = t & 127, kb = t >> 7;
        const float* fp = g_feat + (s0 + s)*8;
        float4 f0 = *(const float4*)fp;
        float4 f1 = *(const float4*)(fp + 4);
        float f[6] = {f0.x, f0.y, f0.z, f0.w, f1.x, f1.y};
        float* dst = &sH[s*HPAD + kb*32];
        #pragma unroll 2
        for (int m = 0; m < 8; m++) {
            float4 hv;
            float* hp = (float*)&hv;
            #pragma unroll
            for (int q = 0; q < 4; q++) {
                int k = kb*32 + m*4 + q;
                float acc = sB1[k];
                #pragma unroll
                for (int c = 0; c < 6; c++) acc += f[c]*sW1[k*6+c];
                hp[q] = fmaxf(acc, 0.f);
            }
            *(float4*)(dst + m*4) = hv;
        }
    }
    __syncthreads();

    int to = t & 15, ts = t >> 4;
    const ull* hrow[8];
    #pragma unroll
    for (int j = 0; j < 8; j++) hrow[j] = (const ull*)&sH[(ts*8 + j)*HPAD];

    // GEMM1: x2[o][s], o = to + 16i
    float h2v[4][8];
    {
        ull acc[32];
        #pragma unroll
        for (int i = 0; i < 32; i++) acc[i] = 0ull;
        const ull* wrow[4];
        #pragma unroll
        for (int i = 0; i < 4; i++) wrow[i] = (const ull*)&sW2[(to + 16*i)*WPAD];
        #pragma unroll 2
        for (int k2 = 0; k2 < 32; k2++) {
            ull wv[4], hv[8];
            #pragma unroll
            for (int i = 0; i < 4; i++) wv[i] = wrow[i][k2];
            #pragma unroll
            for (int j = 0; j < 8; j++) hv[j] = hrow[j][k2];
            #pragma unroll
            for (int i = 0; i < 4; i++)
                #pragma unroll
                for (int j = 0; j < 8; j++) fma2(acc[i*8+j], wv[i], hv[j]);
        }
        #pragma unroll
        for (int i = 0; i < 4; i++) {
            int o = to + 16*i;
            float sc = sc2s[o], sh = sh2s[o];
            #pragma unroll
            for (int j = 0; j < 8; j++)
                h2v[i][j] = fmaxf(hadd2(acc[i*8+j])*sc + sh, 0.f);
        }
    }
    __syncthreads();   // all GEMM1 reads of sH done (sW2 also free now)

    // write h2 into sH[s][k]
    #pragma unroll
    for (int i = 0; i < 4; i++) {
        int o = to + 16*i;
        #pragma unroll
        for (int j = 0; j < 8; j++) sH[(ts*8 + j)*HPAD + o] = h2v[i][j];
    }
    __syncthreads();

    // GEMM2: x3[o][s] in two o-halves; o = half*64 + to + 16i
    for (int half = 0; half < 2; half++) {
        ull acc[32];
        #pragma unroll
        for (int i = 0; i < 32; i++) acc[i] = 0ull;
        const ull* wrow[4];
        #pragma unroll
        for (int i = 0; i < 4; i++) wrow[i] = (const ull*)&sW3[(half*64 + to + 16*i)*WPAD];
        #pragma unroll 2
        for (int k2 = 0; k2 < 32; k2++) {
            ull wv[4], hv[8];
            #pragma unroll
            for (int i = 0; i < 4; i++) wv[i] = wrow[i][k2];
            #pragma unroll
            for (int j = 0; j < 8; j++) hv[j] = hrow[j][k2];
            #pragma unroll
            for (int i = 0; i < 4; i++)
                #pragma unroll
                for (int j = 0; j < 8; j++) fma2(acc[i*8+j], wv[i], hv[j]);
        }
        #pragma unroll
        for (int i = 0; i < 4; i++) {
            int o = half*64 + to + 16*i;
            float ps = 0.f, pq = 0.f, mx = -INFINITY, mn = INFINITY;
            #pragma unroll
            for (int j = 0; j < 8; j++) {
                float x = hadd2(acc[i*8+j]);
                ps += x; pq += x*x; mx = fmaxf(mx, x); mn = fminf(mn, x);
            }
            atomicAdd(&csum[o], ps);
            atomicAdd(&csq[o], pq);
            rmax[ts*128 + o] = mx;   // sW2 region: free after GEMM1 sync
            rmin[ts*128 + o] = mn;
        }
    }
    __syncthreads();

    // reduce 4 ts-rows per group (group = 32 samples)
    for (int v = t; v < 512; v += 256) {
        int gq = v >> 7, o = v & 127;
        float mx = rmax[(gq*4+0)*128 + o];
        mx = fmaxf(mx, rmax[(gq*4+1)*128 + o]);
        mx = fmaxf(mx, rmax[(gq*4+2)*128 + o]);
        mx = fmaxf(mx, rmax[(gq*4+3)*128 + o]);
        float mn = rmin[(gq*4+0)*128 + o];
        mn = fminf(mn, rmin[(gq*4+1)*128 + o]);
        mn = fminf(mn, rmin[(gq*4+2)*128 + o]);
        mn = fminf(mn, rmin[(gq*4+3)*128 + o]);
        size_t g = s0/32 + gq;
        g_gmax[g*128 + o] = mx;
        g_gmin[g*128 + o] = mn;
    }
    __syncthreads();
    if (t < 128) { atomicAdd(&g_x3sum[t], csum[t]); atomicAdd(&g_x3sq[t], csq[t]); }
}

// ---------------- K6: BN3 params ----------------
__global__ void k_bn3(const float* __restrict__ g3, const float* __restrict__ b3) {
    int o = threadIdx.x;  // 128
    const float inv = 1.0f / (float)NSAMPLES;
    float m = g_x3sum[o]*inv;
    float v = fmaxf(g_x3sq[o]*inv - m*m, 0.f);
    float sc = g3[o]*rsqrtf(v + BNEPS);
    g_sc3[o] = sc; g_sh3[o] = b3[o] - m*sc;
}

// ---------------- K7: bn3+relu on group max/min, transposed output ----------------
__global__ void k_out2(float* __restrict__ out2) {
    __shared__ float tr[32*129];
    int b = blockIdx.y;
    int s0 = blockIdx.x * 32;
    for (int i = threadIdx.x; i < 32*128; i += 256) {
        int gi = i >> 7, o = i & 127;
        float sc = g_sc3[o], sh = g_sh3[o];
        size_t g = (size_t)(b*SS + s0 + gi);
        float v = (sc >= 0.f) ? g_gmax[g*128 + o] : g_gmin[g*128 + o];
        tr[gi*129 + o] = fmaxf(sc*v + sh, 0.f);
    }
    __syncthreads();
    for (int i = threadIdx.x; i < 32*128; i += 256) {
        int o = i >> 5, si = i & 31;
        out2[((size_t)(b*128 + o))*SS + s0 + si] = tr[si*129 + o];
    }
}

// ---------------- launch ----------------
extern "C" void kernel_launch(void* const* d_in, const int* in_sizes, int n_in,
                              void* d_out, int out_size) {
    const float* xyz    = (const float*)d_in[0];
    const float* points = (const float*)d_in[1];
    const int*   fps    = (const int*)  d_in[2];
    const float* W1 = (const float*)d_in[3];
    const float* g1 = (const float*)d_in[4];
    const float* b1 = (const float*)d_in[5];
    const float* W2 = (const float*)d_in[6];
    const float* g2 = (const float*)d_in[7];
    const float* b2 = (const float*)d_in[8];
    const float* W3 = (const float*)d_in[9];
    const float* g3 = (const float*)d_in[10];
    const float* b3 = (const float*)d_in[11];

    float* out1 = (float*)d_out;
    float* out2 = (float*)d_out + (size_t)BB*3*SS;

    const int SMEM_BALL  = (3*NN)*4 + 8*32*4;                 // 99328
    const int SMEM_STATS = (512 + 64*P1PAD)*4;                // 36352
    const int SMEM_FUSED = (13504 + 128*HPAD)*4;              // 88832

    cudaFuncSetAttribute(k_ball,  cudaFuncAttributeMaxDynamicSharedMemorySize, SMEM_BALL);
    cudaFuncSetAttribute(k_stats, cudaFuncAttributeMaxDynamicSharedMemorySize, SMEM_STATS);
    cudaFuncSetAttribute(k_fused, cudaFuncAttributeMaxDynamicSharedMemorySize, SMEM_FUSED);

    k_zero<<<1, 256>>>();
    k_ball<<<dim3(SS/32, BB), 256, SMEM_BALL>>>(xyz, points, fps, out1);
    k_bn1<<<1, 64>>>(W1, g1, b1);
    k_stats<<<592, 256, SMEM_STATS>>>();
    k_bn2<<<1, 128>>>(W2, g2, b2);
    k_fused<<<NTILES, 256, SMEM_FUSED>>>(W2, W3);
    k_bn3<<<1, 128>>>(g3, b3);
    k_out2<<<dim3(SS/32, BB), 256>>>(out2);
}